// round 3
// baseline (speedup 1.0000x reference)
#include <cuda_runtime.h>
#include <cuda_bf16.h>

// CostGenerator: cost[b,c,d,h,w] = (w>=d) ? left[b,c,h,w] - right[b,c,h,w-d] : 0
// Shapes fixed by the problem: B=2, C=32, H=128, W=256, D=48 (all f32).
//
// Strategy: pure HBM-write-bound (403 MB out, 16 MB in). One block handles
// 4 rows of one (b,c) plane; right rows staged in smem (48x reuse), left held
// in registers, float4 stores so STG issue cost stays below the DRAM floor.

#define B_  2
#define C_  32
#define H_  128
#define W_  256
#define D_  48
#define ROWS_PER_BLOCK 4
#define THREADS 256   // 64 float4-lanes per row * 4 rows

__global__ __launch_bounds__(THREADS, 8)
void cost_generator_kernel(const float* __restrict__ left,
                           const float* __restrict__ right,
                           float* __restrict__ out)
{
    __shared__ float s_right[ROWS_PER_BLOCK][W_];

    const int tid = threadIdx.x;
    const int r   = tid >> 6;        // row within block: 0..3
    const int v   = tid & 63;        // float4 lane within row: 0..63
    const int w0  = v << 2;          // first w this thread owns

    const int hb  = blockIdx.x % (H_ / ROWS_PER_BLOCK);
    const int bc  = blockIdx.x / (H_ / ROWS_PER_BLOCK);   // fused (b*C + c)
    const int h   = hb * ROWS_PER_BLOCK + r;

    const size_t in_off = ((size_t)bc * H_ + h) * W_;

    // Left values live in registers for the whole d-loop.
    const float4 l4 = *reinterpret_cast<const float4*>(left + in_off + w0);

    // Stage this row of right into shared memory (read once from GMEM,
    // reused 48 times from smem).
    *reinterpret_cast<float4*>(&s_right[r][w0]) =
        *reinterpret_cast<const float4*>(right + in_off + w0);
    __syncthreads();

    const float* sr = s_right[r];

    // Output base for d=0; each d advances by one H*W plane.
    float* op = out + (((size_t)bc * D_) * H_ + h) * W_ + w0;

    #pragma unroll 4
    for (int d = 0; d < D_; ++d) {
        const int i0 = w0 - d;
        // Clamp index so the LDS is always in-bounds; select the zero for
        // invalid (w < d) positions afterwards.
        const float r0 = sr[max(i0,     0)];
        const float r1 = sr[max(i0 + 1, 0)];
        const float r2 = sr[max(i0 + 2, 0)];
        const float r3 = sr[max(i0 + 3, 0)];

        float4 o;
        o.x = (i0     >= 0) ? (l4.x - r0) : 0.0f;
        o.y = (i0 + 1 >= 0) ? (l4.y - r1) : 0.0f;
        o.z = (i0 + 2 >= 0) ? (l4.z - r2) : 0.0f;
        o.w = (i0 + 3 >= 0) ? (l4.w - r3) : 0.0f;

        *reinterpret_cast<float4*>(op) = o;
        op += (size_t)H_ * W_;
    }
}

extern "C" void kernel_launch(void* const* d_in, const int* in_sizes, int n_in,
                              void* d_out, int out_size)
{
    const float* left  = (const float*)d_in[0];
    const float* right = (const float*)d_in[1];
    float* out = (float*)d_out;

    const int grid = B_ * C_ * (H_ / ROWS_PER_BLOCK);   // 2048 blocks
    cost_generator_kernel<<<grid, THREADS>>>(left, right, out);
}